// round 12
// baseline (speedup 1.0000x reference)
#include <cuda_runtime.h>
#include <cuda_bf16.h>
#include <float.h>

// BinsChamferLoss (R12: warp-private slot arrays, ZERO shared-memory atomics).
// sum over (b,p) of min_t | center(b,p) - target(b,t) |, targets masked to 0 below 0.001.
//
// k_prep (B blocks): sort centers, build 2048-cell LUT, publish to global.
// k_main (75 x B = 600 blocks, 256 thr, 1 float4/thr):
//   - each warp owns a private u64[257] accumulator (no cross-warp races)
//   - intra-warp same-slot collisions resolved in registers via __match_any_sync
//     + shuffle gather; group members then perform IDENTICAL plain LDS/STS RMW
//   - merge 8 warp arrays + flush to global scratch, finisher reduces per batch
//
// Slot word: w[i].lo = maxBelow enc for center i   (enc = bits(t)+1; 0 = none)
//            w[i].hi = minAbove enc for center i-1 (enc = ~bits(t);  0 = none)
// (a target with lower_bound == base updates both halves of w[base])

#define MAXB 32
#define P_BINS 256
#define MIN_DEPTH 0.001f
#define LUTN 2048
#define NW (P_BINS + 1)
#define TPB 256
#define NWARPS (TPB / 32)
#define FULLM 0xffffffffu

__device__ float              g_centers[MAXB * P_BINS];
__device__ unsigned short     g_lut[MAXB * LUTN];
__device__ float              g_cmin[MAXB];
__device__ float              g_invw[MAXB];
__device__ unsigned long long g_W[MAXB * NW];   // zero-init = "none"
__device__ float              g_batchSum[MAXB];
__device__ unsigned int       g_cnt[MAXB];
__device__ unsigned int       g_done;

__device__ __forceinline__ unsigned int atom_add_acqrel(unsigned int* p, unsigned int v)
{
    unsigned int old;
    asm volatile("atom.acq_rel.gpu.global.add.u32 %0, [%1], %2;"
                 : "=r"(old) : "l"(p), "r"(v) : "memory");
    return old;
}

// ---------------- Kernel 1: sort centers + LUT, once per batch ------------
__global__ void __launch_bounds__(P_BINS)
k_prep(const float* __restrict__ bins)
{
    const int b   = blockIdx.x;
    const int tid = threadIdx.x;

    __shared__ float sC[P_BINS];

    float v;
    {
        const float* bb = bins + b * (P_BINS + 1);
        v = 0.5f * (bb[tid] + bb[tid + 1]);
    }

#pragma unroll
    for (int k = 2; k <= P_BINS; k <<= 1) {
#pragma unroll
        for (int j = k >> 1; j >= 1; j >>= 1) {
            bool up = ((tid & k) == 0);
            float other;
            if (j >= 32) {
                __syncthreads();
                sC[tid] = v;
                __syncthreads();
                other = sC[tid ^ j];
            } else {
                other = __shfl_xor_sync(FULLM, v, j);
            }
            bool lower = ((tid & j) == 0);
            v = (lower == up) ? fminf(v, other) : fmaxf(v, other);
        }
    }
    __syncthreads();
    sC[tid] = v;
    g_centers[b * P_BINS + tid] = v;
    __syncthreads();

    const float cmin = sC[0];
    const float cmax = sC[P_BINS - 1];
    const float span = cmax - cmin;
    const float invw = (span > 0.0f) ? ((float)LUTN / span) : 0.0f;
    if (tid == 0) { g_cmin[b] = cmin; g_invw[b] = invw; }

    {
        float me = sC[tid];
        int st = min(LUTN, max(0, (int)((me - cmin) * invw)));
        int en;
        if (tid == P_BINS - 1) en = LUTN;
        else {
            float nx = sC[tid + 1];
            en = min(LUTN, max(0, (int)((nx - cmin) * invw)));
        }
        if (tid == 0) st = 0;
        for (int k = st; k < en; ++k) g_lut[b * LUTN + k] = (unsigned short)tid;
    }
}

// ---------------- Kernel 2: scatter (atomic-free smem) + reduce -----------
__global__ void __launch_bounds__(TPB)
k_main(const float* __restrict__ depth, int M, int B, float* __restrict__ out)
{
    const int b    = blockIdx.y;
    const int tid  = threadIdx.x;
    const int lane = tid & 31;
    const int warp = tid >> 5;

    __shared__ float              sC[P_BINS];
    __shared__ unsigned short     sLUT[LUTN];
    __shared__ unsigned long long sWarr[NWARPS][NW];   // warp-private accumulators
    __shared__ unsigned int       wA[NWARPS], wS[NWARPS];
    __shared__ float              wsum[NWARPS];
    __shared__ int                sFinisher;

    // ---- Prologue: load published tables, zero warp arrays ----
    sC[tid] = g_centers[b * P_BINS + tid];
    {
        const unsigned int* lsrc = (const unsigned int*)(g_lut + b * LUTN);
        unsigned int* ldst = (unsigned int*)sLUT;
#pragma unroll
        for (int r = 0; r < LUTN / 2 / TPB; ++r)
            ldst[tid + r * TPB] = lsrc[tid + r * TPB];
    }
#pragma unroll
    for (int w = 0; w < NWARPS; ++w) sWarr[w][tid] = 0ull;
    if (tid < NWARPS) sWarr[tid][P_BINS] = 0ull;
    const float cmin = g_cmin[b];
    const float invw = g_invw[b];
    __syncthreads();

    unsigned long long* warr = sWarr[warp];

    // ---- Scatter: one float4 per thread; zero smem atomics ----
    {
        const float4* tgt4 = (const float4*)(depth + (long long)b * M);
        const int i = blockIdx.x * TPB + tid;        // grid sized so i < M/4 always
        float4 vv = tgt4[i];
        float t[4] = {vv.x, vv.y, vv.z, vv.w};

#pragma unroll
        for (int q = 0; q < 4; ++q) {
            float tq = (t[q] >= MIN_DEPTH) ? t[q] : 0.0f;
            unsigned int tb = __float_as_uint(tq);

            // LUT hint -> exact lower_bound via bidirectional walk
            int k = min(LUTN - 1, max(0, (int)((tq - cmin) * invw)));
            int bs = (int)sLUT[k];
            while (bs > 0 && sC[bs - 1] >= tq) --bs;
            while (bs < P_BINS && sC[bs] < tq) ++bs;
            // bs == lower_bound(sC, tq), in [0, P_BINS]

            // Intra-warp same-slot resolution: group lanes by slot, reduce tb
            unsigned int grp = __match_any_sync(FULLM, bs);
            unsigned int tmax = tb, tmin = tb;
            unsigned int rem = grp & ~(1u << lane);
            while (__ballot_sync(FULLM, rem != 0u)) {
                int src = rem ? (__ffs(rem) - 1) : lane;
                unsigned int o = __shfl_sync(FULLM, tb, src);
                if (rem) {
                    tmax = max(tmax, o);
                    tmin = min(tmin, o);
                    rem &= rem - 1u;
                }
            }

            // Plain RMW into warp-private array (group members write identical values)
            unsigned long long w = warr[bs];
            unsigned int lo = max((unsigned int)w,         tmax + 1u);  // maxBelow enc
            unsigned int hi = max((unsigned int)(w >> 32), ~tmin);      // minAbove enc
            unsigned long long m = ((unsigned long long)hi << 32) | lo;
            if (m != w) warr[bs] = m;
        }
    }
    __syncthreads();

    // ---- Merge warp arrays + flush to global scratch (filtered) ----
    {
#pragma unroll
        for (int rep = 0; rep < 2; ++rep) {
            int idx = (rep == 0) ? tid : P_BINS;
            if (rep == 1 && tid != 0) break;
            unsigned int lo = 0u, hi = 0u;
#pragma unroll
            for (int w = 0; w < NWARPS; ++w) {
                unsigned long long v = sWarr[w][idx];
                lo = max(lo, (unsigned int)v);
                hi = max(hi, (unsigned int)(v >> 32));
            }
            if (lo | hi) {
                unsigned long long* gw = &g_W[b * NW + idx];
                unsigned long long g = *gw;
                unsigned int* p = (unsigned int*)gw;
                if (lo > (unsigned int)g)         atomicMax(p, lo);
                if (hi > (unsigned int)(g >> 32)) atomicMax(p + 1, hi);
            }
        }
    }

    // ---- Last block of this batch reduces it (acq_rel arrive) ----
    if (tid == 0) {
        unsigned int old = atom_add_acqrel(&g_cnt[b], 1u);
        sFinisher = (old == (unsigned)(gridDim.x - 1));
    }
    __syncthreads();
    if (!sFinisher) return;

    unsigned long long w0 = g_W[b * NW + tid];
    unsigned long long w1 = g_W[b * NW + tid + 1];
    __syncthreads();                               // reads before resets
    g_W[b * NW + tid] = 0ull;                      // reset for graph replay
    if (tid == 0) { g_W[b * NW + P_BINS] = 0ull; g_cnt[b] = 0u; }

    unsigned int encA = (unsigned int)w0;          // A[tid]
    unsigned int encS = (unsigned int)(w1 >> 32);  // S[tid]

    // prefix-max / suffix-max scans, shuffle-based
    unsigned int pv = encA;
#pragma unroll
    for (int o = 1; o < 32; o <<= 1) {
        unsigned int n = __shfl_up_sync(FULLM, pv, o);
        if (lane >= o) pv = max(pv, n);
    }
    if (lane == 31) wA[warp] = pv;

    unsigned int sv = encS;
#pragma unroll
    for (int o = 1; o < 32; o <<= 1) {
        unsigned int n = __shfl_down_sync(FULLM, sv, o);
        if (lane + o < 32) sv = max(sv, n);
    }
    if (lane == 0) wS[warp] = sv;
    __syncthreads();

    unsigned int offA = 0u, offS = 0u;
    for (int w = 0; w < warp; ++w)          offA = max(offA, wA[w]);
    for (int w = warp + 1; w < NWARPS; ++w) offS = max(offS, wS[w]);
    pv = max(pv, offA);
    sv = max(sv, offS);

    float c   = sC[tid];
    float dLo = pv ? (c - __uint_as_float(pv - 1u)) : FLT_MAX;
    float dHi = sv ? (__uint_as_float(~sv) - c)     : FLT_MAX;
    float d   = fminf(dLo, dHi);

#pragma unroll
    for (int o = 16; o >= 1; o >>= 1) d += __shfl_down_sync(FULLM, d, o);
    if (lane == 0) wsum[warp] = d;
    __syncthreads();

    if (tid == 0) {
        float s = 0.0f;
        for (int w = 0; w < NWARPS; ++w) s += wsum[w];
        g_batchSum[b] = s;

        unsigned int old = atom_add_acqrel(&g_done, 1u);
        if (old == (unsigned)(B - 1)) {
            float tot = 0.0f;
            for (int i = 0; i < B; ++i) tot += g_batchSum[i];
            out[0] = tot;
            g_done = 0u;   // reset for next replay
        }
    }
}

extern "C" void kernel_launch(void* const* d_in, const int* in_sizes, int n_in,
                              void* d_out, int out_size)
{
    int bi = 0, di = 1;
    if (n_in >= 2 && in_sizes[0] > in_sizes[1]) { bi = 1; di = 0; }
    const float* bins  = (const float*)d_in[bi];
    const float* depth = (const float*)d_in[di];

    const int B = in_sizes[bi] / (P_BINS + 1);
    const int M = in_sizes[di] / B;

    const int M4 = M >> 2;
    const int splits = (M4 + TPB - 1) / TPB;   // 75 for 320x240: one float4/thread

    k_prep<<<B, P_BINS>>>(bins);
    dim3 grid(splits, B);
    k_main<<<grid, TPB>>>(depth, M, B, (float*)d_out);
}

// round 13
// speedup vs baseline: 1.2542x; 1.2542x over previous
#include <cuda_runtime.h>
#include <cuda_bf16.h>
#include <float.h>

// BinsChamferLoss (R13: single launch, in-kernel prep via ready-flag, REDG flush).
// sum over (b,p) of min_t | center(b,p) - target(b,t) |, targets masked to 0 below 0.001.
//
// Grid (75 x B), 256 thr, 1 float4/thr. Block (0,b) sorts the batch's centers,
// builds the LUT, publishes with st.release; other blocks of the batch spin
// (ld.acquire + nanosleep). All blocks then run the R10 scatter, flush with
// no-return red.global.max, and the last-arriving block per batch reduces.
//
// Slot word: w[i].lo = maxBelow enc for center i   (enc = bits(t)+1; 0 = none)
//            w[i].hi = minAbove enc for center i-1 (enc = ~bits(t);  0 = none)

#define MAXB 32
#define P_BINS 256
#define MIN_DEPTH 0.001f
#define LUTN 1024
#define NW (P_BINS + 1)
#define TPB 256

__device__ float              g_centers[MAXB * P_BINS];
__device__ unsigned short     g_lut[MAXB * LUTN];
__device__ float              g_cminw[MAXB * 2];          // {cmin, invw} per batch
__device__ unsigned long long g_W[MAXB * NW];             // zero-init = "none"
__device__ float              g_batchSum[MAXB];
__device__ unsigned int       g_cnt[MAXB];
__device__ unsigned int       g_done;
__device__ unsigned int       g_ready[MAXB];              // zero-init

__device__ __forceinline__ unsigned int atom_add_acqrel(unsigned int* p, unsigned int v)
{
    unsigned int old;
    asm volatile("atom.acq_rel.gpu.global.add.u32 %0, [%1], %2;"
                 : "=r"(old) : "l"(p), "r"(v) : "memory");
    return old;
}
__device__ __forceinline__ void red_max_relaxed(unsigned int* p, unsigned int v)
{
    asm volatile("red.relaxed.gpu.global.max.u32 [%0], %1;" :: "l"(p), "r"(v) : "memory");
}
__device__ __forceinline__ void st_release(unsigned int* p, unsigned int v)
{
    asm volatile("st.release.gpu.global.u32 [%0], %1;" :: "l"(p), "r"(v) : "memory");
}
__device__ __forceinline__ unsigned int ld_acquire(const unsigned int* p)
{
    unsigned int v;
    asm volatile("ld.acquire.gpu.global.u32 %0, [%1];" : "=r"(v) : "l"(p) : "memory");
    return v;
}

__global__ void __launch_bounds__(TPB)
k_all(const float* __restrict__ bins, const float* __restrict__ depth,
      int M, int B, float* __restrict__ out)
{
    const int b    = blockIdx.y;
    const int tid  = threadIdx.x;
    const int lane = tid & 31;
    const int warp = tid >> 5;

    __shared__ float              sC[P_BINS];
    __shared__ unsigned long long sW[NW];
    __shared__ unsigned int       sLUT[LUTN / 2];
    __shared__ unsigned int       wA[8], wS[8];
    __shared__ float              wsum[8];
    __shared__ int                sFinisher;

    // ================= Prep: block (0,b) sorts + publishes ================
    if (blockIdx.x == 0) {
        float v;
        {
            const float* bb = bins + b * (P_BINS + 1);
            v = 0.5f * (bb[tid] + bb[tid + 1]);
        }
#pragma unroll
        for (int k = 2; k <= P_BINS; k <<= 1) {
#pragma unroll
            for (int j = k >> 1; j >= 1; j >>= 1) {
                bool up = ((tid & k) == 0);
                float other;
                if (j >= 32) {
                    __syncthreads();
                    sC[tid] = v;
                    __syncthreads();
                    other = sC[tid ^ j];
                } else {
                    other = __shfl_xor_sync(0xffffffffu, v, j);
                }
                bool lower = ((tid & j) == 0);
                v = (lower == up) ? fminf(v, other) : fmaxf(v, other);
            }
        }
        __syncthreads();
        sC[tid] = v;
        g_centers[b * P_BINS + tid] = v;
        __syncthreads();

        const float cmin = sC[0];
        const float cmax = sC[P_BINS - 1];
        const float span = cmax - cmin;
        const float invw = (span > 0.0f) ? ((float)LUTN / span) : 0.0f;
        if (tid == 0) { g_cminw[b * 2] = cmin; g_cminw[b * 2 + 1] = invw; }

        {
            float me = sC[tid];
            int st = min(LUTN, max(0, (int)((me - cmin) * invw)));
            int en;
            if (tid == P_BINS - 1) en = LUTN;
            else {
                float nx = sC[tid + 1];
                en = min(LUTN, max(0, (int)((nx - cmin) * invw)));
            }
            if (tid == 0) st = 0;
            for (int k = st; k < en; ++k) g_lut[b * LUTN + k] = (unsigned short)tid;
        }
        __syncthreads();
        if (tid == 0) st_release(&g_ready[b], 1u);   // release: tables visible
    } else {
        // Spin until batch b's tables are published (all blocks co-resident;
        // sorter blocks have the lowest bids, so this cannot deadlock).
        if (tid == 0) {
            while (ld_acquire(&g_ready[b]) == 0u) __nanosleep(64);
        }
        __syncthreads();
    }

    // ================= Prologue: load published tables =====================
    sC[tid]         = g_centers[b * P_BINS + tid];
    sLUT[tid]       = ((const unsigned int*)(g_lut + b * LUTN))[tid];
    sLUT[tid + 256] = ((const unsigned int*)(g_lut + b * LUTN))[tid + 256];
    sW[tid]         = 0ull;
    if (tid == 0) sW[P_BINS] = 0ull;
    const float cmin = g_cminw[b * 2];
    const float invw = g_cminw[b * 2 + 1];
    __syncthreads();

    const unsigned short* lut16 = (const unsigned short*)sLUT;

    // ================= Scatter (R10 body, fastest measured) ================
    {
        const float4* tgt4 = (const float4*)(depth + (long long)b * M);
        const int M4 = M >> 2;                     // M % 4 == 0
        const int i = blockIdx.x * TPB + tid;
        if (i < M4) {
            float4 vv = tgt4[i];
            float t[4] = {vv.x, vv.y, vv.z, vv.w};
            int   base[4];
            unsigned int tb[4];

#pragma unroll
            for (int q = 0; q < 4; ++q) {
                t[q] = (t[q] >= MIN_DEPTH) ? t[q] : 0.0f;
                tb[q] = __float_as_uint(t[q]);
                int k = min(LUTN - 1, max(0, (int)((t[q] - cmin) * invw)));
                base[q] = (int)lut16[k];
            }

#pragma unroll
            for (int q = 0; q < 4; ++q) {
                float tq = t[q];
                int bs = base[q];
                while (bs > 0 && sC[bs - 1] >= tq) --bs;
                float cur = 0.0f;
                while (bs < P_BINS) {
                    cur = sC[bs];
                    if (cur < tq) ++bs; else break;
                }
                // bs == lower_bound(sC, tq)

                unsigned long long w = sW[bs];
                unsigned int encA = tb[q] + 1u;
                if (bs < P_BINS && (unsigned int)w < encA)
                    atomicMax((unsigned int*)&sW[bs], encA);

                int ub = bs;
                if (bs < P_BINS && cur == tq) {      // ties ~never; exactness kept
                    ++ub;
                    while (ub < P_BINS && sC[ub] == tq) ++ub;
                }
                unsigned int encS = ~tb[q];
                if (ub > 0) {
                    unsigned int hi = (ub == bs) ? (unsigned int)(w >> 32)
                                                 : ((unsigned int*)&sW[ub])[1];
                    if (hi < encS)
                        atomicMax(((unsigned int*)&sW[ub]) + 1, encS);
                }
            }
        }
    }
    __syncthreads();

    // ================= Flush: no-return REDG, no filter LDG ================
    {
#pragma unroll
        for (int rep = 0; rep < 2; ++rep) {
            int idx = (rep == 0) ? tid : P_BINS;
            if (rep == 1 && tid != 0) break;
            unsigned long long vv = sW[idx];
            if (vv) {
                unsigned int* p = (unsigned int*)&g_W[b * NW + idx];
                unsigned int lo = (unsigned int)vv, hi = (unsigned int)(vv >> 32);
                if (lo) red_max_relaxed(p, lo);
                if (hi) red_max_relaxed(p + 1, hi);
            }
        }
    }

    // ================= Arrive; last block per batch reduces ================
    if (tid == 0) {
        unsigned int old = atom_add_acqrel(&g_cnt[b], 1u);   // release REDGs / acquire on win
        sFinisher = (old == (unsigned)(gridDim.x - 1));
    }
    __syncthreads();
    if (!sFinisher) return;

    unsigned long long w0 = g_W[b * NW + tid];
    unsigned long long w1 = g_W[b * NW + tid + 1];
    __syncthreads();                               // reads before resets
    g_W[b * NW + tid] = 0ull;                      // reset for graph replay
    if (tid == 0) {
        g_W[b * NW + P_BINS] = 0ull;
        g_cnt[b] = 0u;
        g_ready[b] = 0u;                           // re-arm prep flag for replay
    }

    unsigned int encA = (unsigned int)w0;          // A[tid]
    unsigned int encS = (unsigned int)(w1 >> 32);  // S[tid]

    unsigned int pv = encA;
#pragma unroll
    for (int o = 1; o < 32; o <<= 1) {
        unsigned int n = __shfl_up_sync(0xffffffffu, pv, o);
        if (lane >= o) pv = max(pv, n);
    }
    if (lane == 31) wA[warp] = pv;

    unsigned int sv = encS;
#pragma unroll
    for (int o = 1; o < 32; o <<= 1) {
        unsigned int n = __shfl_down_sync(0xffffffffu, sv, o);
        if (lane + o < 32) sv = max(sv, n);
    }
    if (lane == 0) wS[warp] = sv;
    __syncthreads();

    unsigned int offA = 0u, offS = 0u;
    for (int w = 0; w < warp; ++w)     offA = max(offA, wA[w]);
    for (int w = warp + 1; w < 8; ++w) offS = max(offS, wS[w]);
    pv = max(pv, offA);
    sv = max(sv, offS);

    float c   = sC[tid];
    float dLo = pv ? (c - __uint_as_float(pv - 1u)) : FLT_MAX;
    float dHi = sv ? (__uint_as_float(~sv) - c)     : FLT_MAX;
    float d   = fminf(dLo, dHi);

#pragma unroll
    for (int o = 16; o >= 1; o >>= 1) d += __shfl_down_sync(0xffffffffu, d, o);
    if (lane == 0) wsum[warp] = d;
    __syncthreads();

    if (tid == 0) {
        float s = 0.0f;
        for (int w = 0; w < 8; ++w) s += wsum[w];
        g_batchSum[b] = s;

        unsigned int old = atom_add_acqrel(&g_done, 1u);
        if (old == (unsigned)(B - 1)) {
            float tot = 0.0f;
            for (int i = 0; i < B; ++i) tot += g_batchSum[i];
            out[0] = tot;
            g_done = 0u;   // reset for next replay
        }
    }
}

extern "C" void kernel_launch(void* const* d_in, const int* in_sizes, int n_in,
                              void* d_out, int out_size)
{
    int bi = 0, di = 1;
    if (n_in >= 2 && in_sizes[0] > in_sizes[1]) { bi = 1; di = 0; }
    const float* bins  = (const float*)d_in[bi];
    const float* depth = (const float*)d_in[di];

    const int B = in_sizes[bi] / (P_BINS + 1);
    const int M = in_sizes[di] / B;

    const int M4 = M >> 2;
    const int splits = (M4 + TPB - 1) / TPB;   // 75 for 320x240: one float4/thread

    dim3 grid(splits, B);
    k_all<<<grid, TPB>>>(bins, depth, M, B, (float*)d_out);
}